// round 16
// baseline (speedup 1.0000x reference)
#include <cuda_runtime.h>
#include <cuda_fp16.h>
#include <cstdint>

#define C 8
#define L 4096
#define NN 4096
#define D 128
#define V 100000

// ---------------------------------------------------------------------------
// precomputed fp16 embeddings
// ---------------------------------------------------------------------------
__device__ uint32_t g_e16[(size_t)C * NN * 64];   // fp16(E) packed pairs, 8 MB

// ---------------------------------------------------------------------------
// helpers
// ---------------------------------------------------------------------------
__device__ __forceinline__ uint32_t smem_u32(const void* p) {
    uint32_t a;
    asm("{ .reg .u64 t; cvta.to.shared.u64 t, %1; cvt.u32.u64 %0, t; }" : "=r"(a) : "l"(p));
    return a;
}
__device__ __forceinline__ uint32_t pack_h2(float x, float y) {
    __half2 h = __floats2half2_rn(x, y);     // .x = x (low 16 bits)
    return *(uint32_t*)&h;
}
__device__ __forceinline__ void mma_fp16(float c[4], const uint32_t a[4],
                                         uint32_t b0, uint32_t b1) {
    asm volatile("mma.sync.aligned.m16n8k16.row.col.f32.f16.f16.f32 "
                 "{%0,%1,%2,%3}, {%4,%5,%6,%7}, {%8,%9}, {%0,%1,%2,%3};"
                 : "+f"(c[0]), "+f"(c[1]), "+f"(c[2]), "+f"(c[3])
                 : "r"(a[0]), "r"(a[1]), "r"(a[2]), "r"(a[3]), "r"(b0), "r"(b1));
}
#define LDSM4(r0, r1, r2, r3, addr)                                              \
    asm volatile("ldmatrix.sync.aligned.m8n8.x4.shared.b16 {%0,%1,%2,%3}, [%4];" \
                 : "=r"(r0), "=r"(r1), "=r"(r2), "=r"(r3) : "r"(addr))
#define LDSM4T(r0, r1, r2, r3, addr)                                             \
    asm volatile("ldmatrix.sync.aligned.m8n8.x4.trans.shared.b16 {%0,%1,%2,%3}, [%4];" \
                 : "=r"(r0), "=r"(r1), "=r"(r2), "=r"(r3) : "r"(addr))
#define CP16(dst, src) \
    asm volatile("cp.async.cg.shared.global [%0], [%1], 16;" :: "r"(dst), "l"(src))
#define CP_COMMIT() asm volatile("cp.async.commit_group;" ::: "memory")
#define CP_WAIT0()  asm volatile("cp.async.wait_group 0;" ::: "memory")

// ---------------------------------------------------------------------------
// Kernel 1: gather + fp16 precompute (dtype self-detect via odd-word probe:
// int64 little-endian => odd int32 words are zero high-halves)
// ---------------------------------------------------------------------------
__global__ void gather_kernel(const int* __restrict__ ngram32, const float* __restrict__ Wemb) {
    int f4 = blockIdx.x * blockDim.x + threadIdx.x;   // 0 .. C*N*32-1
    int d4 = f4 & 31;
    int idx = f4 >> 5;                                // c*NN + n
    int probe = ngram32[1] | ngram32[3] | ngram32[5] | ngram32[7];
    int tok = (probe == 0) ? ngram32[2 * idx] : ngram32[idx];
    float4 v = ((const float4*)Wemb)[(size_t)tok * 32 + d4];
    g_e16[(size_t)idx * 64 + d4 * 2 + 0] = pack_h2(v.x, v.y);
    g_e16[(size_t)idx * 64 + d4 * 2 + 1] = pack_h2(v.z, v.w);
}

// ---------------------------------------------------------------------------
// smem layout (bytes). fp16 tiles, 68-word rows (128 fp16 + 8 pad).
//   H: [128][68]    E: [64][68] x2 buffers    Rd: 128 floats
// ---------------------------------------------------------------------------
#define HSTR 68
#define ESTR 68
#define EBUF  17408u
#define OFF_H 0u
#define OFF_E 34816u
#define OFF_RED 69632u
#define SMEM_TOTAL 70144u

// ---------------------------------------------------------------------------
// Kernel 2: fused attention. grid=(L/128, C), block=256 (8 warps), 2 CTAs/SM.
// Warp owns 16 l-rows. GEMM1 split into two 32-col n-halves: each half's S
// (16 regs) is exp'd + packed to fp16 A-fragments immediately, then reused.
// Mask loads for each half issue one phase ahead (latency covered by MMA).
// GEMM2: 16l x 128d, A from packed pa regs (C-frag == A-frag identity).
// ---------------------------------------------------------------------------
__global__ __launch_bounds__(256, 2)
void attn_kernel(const float* __restrict__ H,
                 const float* __restrict__ mask,
                 float* __restrict__ out) {
    extern __shared__ char sm[];
    const uint32_t smb = smem_u32(sm);
    uint32_t* Hs = (uint32_t*)(sm + OFF_H);
    float*    Rd = (float*)(sm + OFF_RED);

    const int t = threadIdx.x, lane = t & 31, wm = t >> 5;
    const int g = lane >> 2, tig = lane & 3;
    const int lane8 = lane & 7, lm = lane >> 3;
    const int c = blockIdx.y, l0 = blockIdx.x * 128;

    // ---- load H tile [128 l][128 d] as fp16 ----
    #pragma unroll
    for (int j = 0; j < 16; j++) {
        int i = t + 256 * j;
        int row = i >> 5, c4 = i & 31;
        float4 v = ((const float4*)H)[(size_t)(l0 + row) * 32 + c4];
        Hs[row * HSTR + c4 * 2 + 0] = pack_h2(v.x, v.y);
        Hs[row * HSTR + c4 * 2 + 1] = pack_h2(v.z, v.w);
    }
    if (t < 128) Rd[t] = 0.0f;

    float O[16][4];
    #pragma unroll
    for (int a = 0; a < 16; a++)
        #pragma unroll
        for (int q = 0; q < 4; q++) O[a][q] = 0.0f;
    float rs[2] = {0.f, 0.f};

    const float INV_T = 0.08838834764831845f;
    const size_t ebase = (size_t)c * NN;
    // per-lane mask row pointers (h=0: row g, h=1: row g+8); col base 2*tig
    const float* mrow0 = mask + ((size_t)c * L + (l0 + 16 * wm + g)) * NN + 2 * tig;
    const float* mrow1 = mrow0 + (size_t)8 * NN;

    // ldmatrix lane-base addresses
    const uint32_t aH = smb + OFF_H +
        (uint32_t)((16 * wm + (lm & 1) * 8 + lane8) * HSTR + (lm >> 1) * 4) * 4u;
    uint32_t bB[4];                       // GEMM1 B: E rows [n][k], rel to ebuf
    #pragma unroll
    for (int p = 0; p < 4; p++) {
        int row = (2 * p + (lm >> 1)) * 8 + lane8;
        bB[p] = (uint32_t)(row * ESTR + (lm & 1) * 4) * 4u;
    }
    // GEMM2 B via ldmatrix.trans on E[n][d], rel to ebuf
    const uint32_t bTr = (uint32_t)(((lm & 1) * 8 + lane8) * (ESTR * 4))
                       + (uint32_t)((lm >> 1) * 16);

    // ---- E-tile copy (cp.async): 64 rows x 256B, 4 chunks/thread ----
    auto issue_copy = [&](int n0, int buf) {
        const uint32_t* srcE = g_e16 + (ebase + n0) * 64;
        uint32_t dst = smb + OFF_E + (uint32_t)buf * EBUF;
        #pragma unroll
        for (int j = 0; j < 4; j++) {
            int i = t + 256 * j;
            int row = i >> 4, c16 = i & 15;
            CP16(dst + (uint32_t)(row * ESTR + c16 * 4) * 4u,
                 srcE + row * 64 + c16 * 4);
        }
        CP_COMMIT();
    };

    issue_copy(0, 0);

    for (int tt = 0; tt < 64; tt++) {
        const int n0 = tt * 64;
        const uint32_t ebuf = smb + OFF_E + (uint32_t)(tt & 1) * EBUF;
        CP_WAIT0();
        __syncthreads();   // E(tt) visible; all warps done with tt-1

        // prefetch E(tt+1) into the buffer freed at the sync
        if (tt < 63) issue_copy(n0 + 64, (tt + 1) & 1);

        uint32_t pa[4][4];   // packed P A-fragments, filled per half

        // ---- mask half A (cols 0..31) — covered by GEMM1 half A ----
        float2 mA[2][4];
        #pragma unroll
        for (int nc = 0; nc < 4; nc++) {
            mA[0][nc] = *(const float2*)&mrow0[n0 + 8 * nc];
            mA[1][nc] = *(const float2*)&mrow1[n0 + 8 * nc];
        }

        // ---- GEMM1 half A: S[16m x 32n], n-cols 0..31 ----
        float S[4][4];
        #pragma unroll
        for (int a = 0; a < 4; a++)
            #pragma unroll
            for (int q = 0; q < 4; q++) S[a][q] = 0.0f;
        #pragma unroll
        for (int kk = 0; kk < 8; kk++) {
            const uint32_t kb = (uint32_t)kk * 32u;
            uint32_t ah[4], r0, r1, r2, r3;
            LDSM4(ah[0], ah[1], ah[2], ah[3], aH + kb);
            LDSM4(r0, r1, r2, r3, ebuf + bB[0] + kb);
            mma_fp16(S[0], ah, r0, r1);
            mma_fp16(S[1], ah, r2, r3);
            LDSM4(r0, r1, r2, r3, ebuf + bB[1] + kb);
            mma_fp16(S[2], ah, r0, r1);
            mma_fp16(S[3], ah, r2, r3);
        }

        // ---- mask half B (cols 32..63) — covered by exp-A + GEMM1 half B ----
        float2 mB[2][4];
        #pragma unroll
        for (int nc = 0; nc < 4; nc++) {
            mB[0][nc] = *(const float2*)&mrow0[n0 + 32 + 8 * nc];
            mB[1][nc] = *(const float2*)&mrow1[n0 + 32 + 8 * nc];
        }

        // ---- exp half A -> pa[0..1] ----
        #pragma unroll
        for (int nc = 0; nc < 4; nc++) {
            float p0 = __expf(S[nc][0] * INV_T) * __saturatef(mA[0][nc].x);
            float p1 = __expf(S[nc][1] * INV_T) * __saturatef(mA[0][nc].y);
            float p2 = __expf(S[nc][2] * INV_T) * __saturatef(mA[1][nc].x);
            float p3 = __expf(S[nc][3] * INV_T) * __saturatef(mA[1][nc].y);
            rs[0] += p0 + p1;
            rs[1] += p2 + p3;
            pa[nc >> 1][(nc & 1) * 2 + 0] = pack_h2(p0, p1);
            pa[nc >> 1][(nc & 1) * 2 + 1] = pack_h2(p2, p3);
        }

        // ---- GEMM1 half B: n-cols 32..63 (S reused) ----
        #pragma unroll
        for (int a = 0; a < 4; a++)
            #pragma unroll
            for (int q = 0; q < 4; q++) S[a][q] = 0.0f;
        #pragma unroll
        for (int kk = 0; kk < 8; kk++) {
            const uint32_t kb = (uint32_t)kk * 32u;
            uint32_t ah[4], r0, r1, r2, r3;
            LDSM4(ah[0], ah[1], ah[2], ah[3], aH + kb);
            LDSM4(r0, r1, r2, r3, ebuf + bB[2] + kb);
            mma_fp16(S[0], ah, r0, r1);
            mma_fp16(S[1], ah, r2, r3);
            LDSM4(r0, r1, r2, r3, ebuf + bB[3] + kb);
            mma_fp16(S[2], ah, r0, r1);
            mma_fp16(S[3], ah, r2, r3);
        }

        // ---- exp half B -> pa[2..3] ----
        #pragma unroll
        for (int nc = 0; nc < 4; nc++) {
            float p0 = __expf(S[nc][0] * INV_T) * __saturatef(mB[0][nc].x);
            float p1 = __expf(S[nc][1] * INV_T) * __saturatef(mB[0][nc].y);
            float p2 = __expf(S[nc][2] * INV_T) * __saturatef(mB[1][nc].x);
            float p3 = __expf(S[nc][3] * INV_T) * __saturatef(mB[1][nc].y);
            rs[0] += p0 + p1;
            rs[1] += p2 + p3;
            pa[2 + (nc >> 1)][(nc & 1) * 2 + 0] = pack_h2(p0, p1);
            pa[2 + (nc >> 1)][(nc & 1) * 2 + 1] = pack_h2(p2, p3);
        }

        // ---- GEMM2: O[16l x 128d] += P x E ----
        #pragma unroll
        for (int kc = 0; kc < 4; kc++) {
            const uint32_t kbase = ebuf + bTr + (uint32_t)kc * (16u * ESTR * 4u);
            #pragma unroll
            for (int j = 0; j < 8; j++) {
                uint32_t b0, b1, b2, b3;
                LDSM4T(b0, b1, b2, b3, kbase + (uint32_t)j * 32u);
                mma_fp16(O[2 * j + 0], pa[kc], b0, b1);
                mma_fp16(O[2 * j + 1], pa[kc], b2, b3);
            }
        }
    }

    // ---- rowsum: quad reduce, exclusive row ownership -> plain store ----
    #pragma unroll
    for (int h = 0; h < 2; h++) {
        float v = rs[h];
        v += __shfl_xor_sync(0xFFFFFFFFu, v, 1);
        v += __shfl_xor_sync(0xFFFFFFFFu, v, 2);
        if (tig == 0) Rd[16 * wm + g + 8 * h] = v;
    }
    __syncthreads();

    // ---- normalize + writeout ----
    #pragma unroll
    for (int h = 0; h < 2; h++) {
        int row = 16 * wm + g + 8 * h;
        float inv = 1.0f / (Rd[row] + 1e-10f);
        float* orow = out + (size_t)(l0 + row) * (C * D) + c * D;
        #pragma unroll
        for (int j = 0; j < 16; j++)
            *(float2*)&orow[8 * j + 2 * tig] =
                make_float2(O[j][2 * h + 0] * inv, O[j][2 * h + 1] * inv);
    }
}

// ---------------------------------------------------------------------------
extern "C" void kernel_launch(void* const* d_in, const int* in_sizes, int n_in,
                              void* d_out, int out_size) {
    const int*   ngram32 = (const int*)d_in[0];
    const float* H       = (const float*)d_in[1];
    const float* mask    = (const float*)d_in[2];
    const float* Wemb    = (const float*)d_in[4];
    float*       out     = (float*)d_out;

    cudaFuncSetAttribute(attn_kernel, cudaFuncAttributeMaxDynamicSharedMemorySize, SMEM_TOTAL);

    gather_kernel<<<C * NN * (D / 4) / 256, 256>>>(ngram32, Wemb);
    dim3 grid(L / 128, C);
    attn_kernel<<<grid, 256, SMEM_TOTAL>>>(H, mask, out);
}

// round 17
// speedup vs baseline: 1.4345x; 1.4345x over previous
#include <cuda_runtime.h>
#include <cuda_fp16.h>
#include <cstdint>

#define C 8
#define L 4096
#define NN 4096
#define D 128
#define V 100000

// ---------------------------------------------------------------------------
// precomputed fp16 embeddings
// ---------------------------------------------------------------------------
__device__ uint32_t g_e16[(size_t)C * NN * 64];   // fp16(E) packed pairs, 8 MB

// ---------------------------------------------------------------------------
// helpers
// ---------------------------------------------------------------------------
__device__ __forceinline__ uint32_t smem_u32(const void* p) {
    uint32_t a;
    asm("{ .reg .u64 t; cvta.to.shared.u64 t, %1; cvt.u32.u64 %0, t; }" : "=r"(a) : "l"(p));
    return a;
}
__device__ __forceinline__ uint32_t pack_h2(float x, float y) {
    __half2 h = __floats2half2_rn(x, y);     // .x = x (low 16 bits)
    return *(uint32_t*)&h;
}
__device__ __forceinline__ void mma_fp16(float c[4], const uint32_t a[4],
                                         uint32_t b0, uint32_t b1) {
    asm volatile("mma.sync.aligned.m16n8k16.row.col.f32.f16.f16.f32 "
                 "{%0,%1,%2,%3}, {%4,%5,%6,%7}, {%8,%9}, {%0,%1,%2,%3};"
                 : "+f"(c[0]), "+f"(c[1]), "+f"(c[2]), "+f"(c[3])
                 : "r"(a[0]), "r"(a[1]), "r"(a[2]), "r"(a[3]), "r"(b0), "r"(b1));
}
#define LDSM4(r0, r1, r2, r3, addr)                                              \
    asm volatile("ldmatrix.sync.aligned.m8n8.x4.shared.b16 {%0,%1,%2,%3}, [%4];" \
                 : "=r"(r0), "=r"(r1), "=r"(r2), "=r"(r3) : "r"(addr))
#define LDSM4T(r0, r1, r2, r3, addr)                                             \
    asm volatile("ldmatrix.sync.aligned.m8n8.x4.trans.shared.b16 {%0,%1,%2,%3}, [%4];" \
                 : "=r"(r0), "=r"(r1), "=r"(r2), "=r"(r3) : "r"(addr))
#define CP16(dst, src) \
    asm volatile("cp.async.cg.shared.global [%0], [%1], 16;" :: "r"(dst), "l"(src))
#define CP_COMMIT() asm volatile("cp.async.commit_group;" ::: "memory")
#define CP_WAIT0()  asm volatile("cp.async.wait_group 0;" ::: "memory")

// ---------------------------------------------------------------------------
// Kernel 1: gather + fp16 precompute (dtype self-detect via odd-word probe:
// int64 little-endian => odd int32 words are zero high-halves)
// ---------------------------------------------------------------------------
__global__ void gather_kernel(const int* __restrict__ ngram32, const float* __restrict__ Wemb) {
    int f4 = blockIdx.x * blockDim.x + threadIdx.x;   // 0 .. C*N*32-1
    int d4 = f4 & 31;
    int idx = f4 >> 5;                                // c*NN + n
    int probe = ngram32[1] | ngram32[3] | ngram32[5] | ngram32[7];
    int tok = (probe == 0) ? ngram32[2 * idx] : ngram32[idx];
    float4 v = ((const float4*)Wemb)[(size_t)tok * 32 + d4];
    g_e16[(size_t)idx * 64 + d4 * 2 + 0] = pack_h2(v.x, v.y);
    g_e16[(size_t)idx * 64 + d4 * 2 + 1] = pack_h2(v.z, v.w);
}

// ---------------------------------------------------------------------------
// smem layout (bytes). fp16 tiles, 68-word rows (128 fp16 + 8 pad).
//   H: [128][68]  E: [64][68] x2  M(mask): [128][72 floats]  Rd: 128 floats
//   Mask stride 72 words (mod 32 = 8): epilogue float2 reads conflict-free
//   per 16-lane phase (banks 8g + 2tig distinct).
// ---------------------------------------------------------------------------
#define HSTR 68
#define ESTR 68
#define MSTRB 288u               // mask row stride in bytes (72 words)
#define EBUF  17408u
#define OFF_H 0u
#define OFF_E 34816u
#define OFF_M 69632u
#define OFF_RED 106496u
#define SMEM_TOTAL 107008u

// ---------------------------------------------------------------------------
// Kernel 2: fused attention. grid=(L/128, C), block=256 (8 warps), 2 CTAs/SM.
// R12 structure (warp owns 16 l-rows; GEMM1 16m x 64n; S->pa in regs;
// GEMM2 16l x 128d) + mask staged through smem via cp.async so the epilogue
// reads LDS (29 cyc) instead of an uncovered DRAM LDG (~600 cyc).
// ---------------------------------------------------------------------------
__global__ __launch_bounds__(256, 2)
void attn_kernel(const float* __restrict__ H,
                 const float* __restrict__ mask,
                 float* __restrict__ out) {
    extern __shared__ char sm[];
    const uint32_t smb = smem_u32(sm);
    uint32_t* Hs = (uint32_t*)(sm + OFF_H);
    float*    Rd = (float*)(sm + OFF_RED);

    const int t = threadIdx.x, lane = t & 31, wm = t >> 5;
    const int g = lane >> 2, tig = lane & 3;
    const int lane8 = lane & 7, lm = lane >> 3;
    const int c = blockIdx.y, l0 = blockIdx.x * 128;

    // ---- load H tile [128 l][128 d] as fp16 ----
    #pragma unroll
    for (int j = 0; j < 16; j++) {
        int i = t + 256 * j;
        int row = i >> 5, c4 = i & 31;
        float4 v = ((const float4*)H)[(size_t)(l0 + row) * 32 + c4];
        Hs[row * HSTR + c4 * 2 + 0] = pack_h2(v.x, v.y);
        Hs[row * HSTR + c4 * 2 + 1] = pack_h2(v.z, v.w);
    }
    if (t < 128) Rd[t] = 0.0f;

    float O[16][4];
    #pragma unroll
    for (int a = 0; a < 16; a++)
        #pragma unroll
        for (int q = 0; q < 4; q++) O[a][q] = 0.0f;
    float rs[2] = {0.f, 0.f};

    const float INV_T = 0.08838834764831845f;
    const size_t ebase = (size_t)c * NN;
    const float* mtile = mask + ((size_t)c * L + l0) * NN;   // [128 rows][NN]

    // ldmatrix lane-base addresses
    const uint32_t aH = smb + OFF_H +
        (uint32_t)((16 * wm + (lm & 1) * 8 + lane8) * HSTR + (lm >> 1) * 4) * 4u;
    uint32_t bB[4];                       // GEMM1 B: E rows [n][k], rel to ebuf
    #pragma unroll
    for (int p = 0; p < 4; p++) {
        int row = (2 * p + (lm >> 1)) * 8 + lane8;
        bB[p] = (uint32_t)(row * ESTR + (lm & 1) * 4) * 4u;
    }
    // GEMM2 B via ldmatrix.trans on E[n][d], rel to ebuf
    const uint32_t bTr = (uint32_t)(((lm & 1) * 8 + lane8) * (ESTR * 4))
                       + (uint32_t)((lm >> 1) * 16);

    // ---- E-tile copy (cp.async): 64 rows x 256B, 4 chunks/thread ----
    auto issue_copy = [&](int n0, int buf) {
        const uint32_t* srcE = g_e16 + (ebase + n0) * 64;
        uint32_t dst = smb + OFF_E + (uint32_t)buf * EBUF;
        #pragma unroll
        for (int j = 0; j < 4; j++) {
            int i = t + 256 * j;
            int row = i >> 4, c16 = i & 15;
            CP16(dst + (uint32_t)(row * ESTR + c16 * 4) * 4u,
                 srcE + row * 64 + c16 * 4);
        }
        CP_COMMIT();
    };
    // ---- mask-tile copy (cp.async): 128 rows x 256B, 8 chunks/thread ----
    auto issue_mask = [&](int n0) {
        const float* srcM = mtile + n0;
        #pragma unroll
        for (int j = 0; j < 8; j++) {
            int i = t + 256 * j;
            int row = i >> 4, c16 = i & 15;
            CP16(smb + OFF_M + (uint32_t)row * MSTRB + (uint32_t)c16 * 16u,
                 srcM + (size_t)row * NN + c16 * 4);
        }
        CP_COMMIT();
    };

    issue_copy(0, 0);
    issue_mask(0);

    for (int tt = 0; tt < 64; tt++) {
        const int n0 = tt * 64;
        const uint32_t ebuf = smb + OFF_E + (uint32_t)(tt & 1) * EBUF;
        CP_WAIT0();
        __syncthreads();   // E(tt)+mask(tt) visible; all warps done with tt-1

        // prefetch E(tt+1) into the buffer freed at the sync
        if (tt < 63) issue_copy(n0 + 64, (tt + 1) & 1);

        // ---- GEMM1: S[16m x 64n] = H x E^T ----
        float S[8][4];
        #pragma unroll
        for (int a = 0; a < 8; a++)
            #pragma unroll
            for (int q = 0; q < 4; q++) S[a][q] = 0.0f;

        #pragma unroll
        for (int kk = 0; kk < 8; kk++) {
            const uint32_t kb = (uint32_t)kk * 32u;
            uint32_t ah[4];
            LDSM4(ah[0], ah[1], ah[2], ah[3], aH + kb);
            #pragma unroll
            for (int p = 0; p < 4; p++) {
                uint32_t r0, r1, r2, r3;
                LDSM4(r0, r1, r2, r3, ebuf + bB[p] + kb);
                mma_fp16(S[2 * p + 0], ah, r0, r1);
                mma_fp16(S[2 * p + 1], ah, r2, r3);
            }
        }

        // ---- epilogue: P = exp(S/temper)*clip(mask from smem) ----
        #pragma unroll
        for (int h = 0; h < 2; h++) {
            const char* mr = sm + OFF_M + (16 * wm + g + 8 * h) * MSTRB + 2 * tig * 4;
            #pragma unroll
            for (int nc = 0; nc < 8; nc++) {
                float2 m = *(const float2*)(mr + nc * 32);
                float p0 = __expf(S[nc][2 * h + 0] * INV_T) * __saturatef(m.x);
                float p1 = __expf(S[nc][2 * h + 1] * INV_T) * __saturatef(m.y);
                rs[h] += p0 + p1;
                S[nc][2 * h + 0] = p0;
                S[nc][2 * h + 1] = p1;
            }
        }
        __syncthreads();   // all epilogue mask reads done -> mask buffer free

        // prefetch mask(tt+1): covered by GEMM2(tt) + GEMM1(tt+1)
        if (tt < 63) issue_mask(n0 + 64);

        // ---- GEMM2: O[16l x 128d] += P x E ; A packed from S accumulators ----
        #pragma unroll
        for (int kc = 0; kc < 4; kc++) {
            uint32_t pa[4];
            pa[0] = pack_h2(S[2 * kc + 0][0], S[2 * kc + 0][1]);   // (g,   k0..1)
            pa[1] = pack_h2(S[2 * kc + 0][2], S[2 * kc + 0][3]);   // (g+8, k0..1)
            pa[2] = pack_h2(S[2 * kc + 1][0], S[2 * kc + 1][1]);   // (g,   k8..9)
            pa[3] = pack_h2(S[2 * kc + 1][2], S[2 * kc + 1][3]);   // (g+8, k8..9)
            const uint32_t kbase = ebuf + bTr + (uint32_t)kc * (16u * ESTR * 4u);
            #pragma unroll
            for (int j = 0; j < 8; j++) {
                uint32_t b0, b1, b2, b3;
                LDSM4T(b0, b1, b2, b3, kbase + (uint32_t)j * 32u);
                mma_fp16(O[2 * j + 0], pa, b0, b1);
                mma_fp16(O[2 * j + 1], pa, b2, b3);
            }
        }
    }

    // ---- rowsum: quad reduce, exclusive row ownership -> plain store ----
    #pragma unroll
    for (int h = 0; h < 2; h++) {
        float v = rs[h];
        v += __shfl_xor_sync(0xFFFFFFFFu, v, 1);
        v += __shfl_xor_sync(0xFFFFFFFFu, v, 2);
        if (tig == 0) Rd[16 * wm + g + 8 * h] = v;
    }
    __syncthreads();

    // ---- normalize + writeout ----
    #pragma unroll
    for (int h = 0; h < 2; h++) {
        int row = 16 * wm + g + 8 * h;
        float inv = 1.0f / (Rd[row] + 1e-10f);
        float* orow = out + (size_t)(l0 + row) * (C * D) + c * D;
        #pragma unroll
        for (int j = 0; j < 16; j++)
            *(float2*)&orow[8 * j + 2 * tig] =
                make_float2(O[j][2 * h + 0] * inv, O[j][2 * h + 1] * inv);
    }
}

// ---------------------------------------------------------------------------
extern "C" void kernel_launch(void* const* d_in, const int* in_sizes, int n_in,
                              void* d_out, int out_size) {
    const int*   ngram32 = (const int*)d_in[0];
    const float* H       = (const float*)d_in[1];
    const float* mask    = (const float*)d_in[2];
    const float* Wemb    = (const float*)d_in[4];
    float*       out     = (float*)d_out;

    cudaFuncSetAttribute(attn_kernel, cudaFuncAttributeMaxDynamicSharedMemorySize, SMEM_TOTAL);

    gather_kernel<<<C * NN * (D / 4) / 256, 256>>>(ngram32, Wemb);
    dim3 grid(L / 128, C);
    attn_kernel<<<grid, 256, SMEM_TOTAL>>>(H, mask, out);
}